// round 16
// baseline (speedup 1.0000x reference)
#include <cuda_runtime.h>
#include <cuda_fp16.h>
#include <cstdint>

// GMEdgeConv, fp16 storage + fp16 mma.sync edge GEMM, occupancy-first,
// 32-edge chunks (2 tiles) per warp iteration to amortize L2 latency.
// branch_kernel uses DYNAMIC smem (static __shared__ is capped at 48KB).
//   Stage 1 (node_kernel, fp32 math): g_UVh[n] = fp16([x@(Wt1a-Wt1b) | x@Wt1b+bt1 | x@(Wg1a-Wg1b) | x@Wg1b+bg1])
//   Stage 2 (branch_kernel x2, sequential): 10 warps/CTA, 3 CTAs/SM (30 warps/SM);
//       per warp iteration: gather 32 edges (16 independent LDG.128, MLP 16),
//       h1 = relu(U+V') combined in registers -> 2 SMEM tiles,
//       then 2x { MMA m16n8k16.f16 tile + relu(D+b2) + zero-skip filtered atomicMax }.
//   Stage 3 (final_kernel, fp32, 2 CTAs/SM): out = relu([pool_t|pool_g] @ Wf + bf)

#define N_MAX 100000

__device__ float  g_pool[2][(size_t)N_MAX * 64];
__device__ __half g_UVh[(size_t)N_MAX * 256];

// D += A(16x16 f16) @ B(16x8 f16), fp32 accum
__device__ __forceinline__ void mma_f16(float* c, const uint32_t* a,
                                        uint32_t b0, uint32_t b1) {
    asm volatile(
        "mma.sync.aligned.m16n8k16.row.col.f32.f16.f16.f32 "
        "{%0,%1,%2,%3}, {%4,%5,%6,%7}, {%8,%9}, {%0,%1,%2,%3};\n"
        : "+f"(c[0]), "+f"(c[1]), "+f"(c[2]), "+f"(c[3])
        : "r"(a[0]), "r"(a[1]), "r"(a[2]), "r"(a[3]), "r"(b0), "r"(b1));
}

__device__ __forceinline__ uint32_t hrelu_add(uint32_t u, uint32_t v) {
    __half2 z = __float2half2_rn(0.f);
    __half2 r = __hmax2(__hadd2(*(__half2*)&u, *(__half2*)&v), z);
    return *(uint32_t*)&r;
}

// ---------------------------------------------------------------------------
// Stage 1: node projections (fp32 math, fp16 store), b1 folded into V columns.
// ---------------------------------------------------------------------------
__global__ __launch_bounds__(512, 1)
void node_kernel(const float* __restrict__ x,
                 const float* __restrict__ Wt1, const float* __restrict__ Wg1,
                 const float* __restrict__ bt1, const float* __restrict__ bg1,
                 int nN)
{
    extern __shared__ float sm[];
    float* Wc = sm;              // 64 x 260 (cols: Ut|Vt|Ug|Vg)
    float* As = Wc + 64 * 260;   // 128 x 68

    const int tid = threadIdx.x;
    const int tx  = tid & 31;
    const int ty  = tid >> 5;

    for (int idx = tid; idx < 64 * 256; idx += 512) {
        int k = idx >> 8, c = idx & 255;
        float v;
        if (c < 64)        v = Wt1[k * 64 + c] - Wt1[(64 + k) * 64 + c];
        else if (c < 128)  v = Wt1[(64 + k) * 64 + (c - 64)];
        else if (c < 192)  v = Wg1[k * 64 + (c - 128)] - Wg1[(64 + k) * 64 + (c - 128)];
        else               v = Wg1[(64 + k) * 64 + (c - 192)];
        Wc[k * 260 + c] = v;
    }

    const int base = blockIdx.x * 128;
    for (int idx = tid; idx < 128 * 16; idx += 512) {
        int nd = idx >> 4, q = idx & 15;
        float4 v = make_float4(0.f, 0.f, 0.f, 0.f);
        if (base + nd < nN) v = *(const float4*)(x + (size_t)(base + nd) * 64 + 4 * q);
        *(float4*)(As + nd * 68 + 4 * q) = v;
    }
    __syncthreads();

    #pragma unroll
    for (int p = 0; p < 2; p++) {
        const int c = p * 128 + 4 * tx;
        float acc[8][4];
        #pragma unroll
        for (int ii = 0; ii < 8; ii++)
            #pragma unroll
            for (int j = 0; j < 4; j++) acc[ii][j] = 0.f;

        #pragma unroll 4
        for (int k = 0; k < 64; k += 4) {
            float4 w0 = *(const float4*)(Wc + (k + 0) * 260 + c);
            float4 w1 = *(const float4*)(Wc + (k + 1) * 260 + c);
            float4 w2 = *(const float4*)(Wc + (k + 2) * 260 + c);
            float4 w3 = *(const float4*)(Wc + (k + 3) * 260 + c);
            #pragma unroll
            for (int ii = 0; ii < 8; ii++) {
                float4 a = *(const float4*)(As + (8 * ty + ii) * 68 + k);
                acc[ii][0] += a.x * w0.x + a.y * w1.x + a.z * w2.x + a.w * w3.x;
                acc[ii][1] += a.x * w0.y + a.y * w1.y + a.z * w2.y + a.w * w3.y;
                acc[ii][2] += a.x * w0.z + a.y * w1.z + a.z * w2.z + a.w * w3.z;
                acc[ii][3] += a.x * w0.w + a.y * w1.w + a.z * w2.w + a.w * w3.w;
            }
        }
        float4 bv = make_float4(0.f, 0.f, 0.f, 0.f);
        if (4 * tx >= 64) {
            const float* bp = (p ? bg1 : bt1) + (4 * tx - 64);
            bv = *(const float4*)bp;
        }
        #pragma unroll
        for (int ii = 0; ii < 8; ii++) {
            int node = base + 8 * ty + ii;
            if (node < nN) {
                __half2 h0 = __float22half2_rn(make_float2(acc[ii][0] + bv.x,
                                                           acc[ii][1] + bv.y));
                __half2 h1 = __float22half2_rn(make_float2(acc[ii][2] + bv.z,
                                                           acc[ii][3] + bv.w));
                uint2 pk;
                pk.x = *(uint32_t*)&h0;
                pk.y = *(uint32_t*)&h1;
                *(uint2*)(g_UVh + (size_t)node * 256 + c) = pk;
            }
        }
    }
}

// ---------------------------------------------------------------------------
// Stage 2: warp-level fp16 MMA edge GEMM + segment max, 30 warps/SM,
// 32-edge chunks (2 tiles). Launched once per branch (sequential).
// DYNAMIC smem/CTA: W2T 9216B + b2s 256B + 10 x 2 x 2304B = 55552B -> 3 CTAs/SM.
// ---------------------------------------------------------------------------
#define BWARPS 10
#define SMEM_BRANCH (9216 + 256 + BWARPS * 2 * 2304)
__global__ __launch_bounds__(32 * BWARPS, 3)
void branch_kernel(const int* __restrict__ ei,
                   const float* __restrict__ W2, const float* __restrict__ b2,
                   int nE, int br)
{
    extern __shared__ __align__(16) char smRaw[];
    __half* W2T = (__half*)smRaw;                    // [n][k], stride 72 (9216B)
    float*  b2s = (float*)(smRaw + 9216);            // 64 floats (256B)
    __half* Tiles = (__half*)(smRaw + 9472);         // [warp][2][16*72]

    const int tid  = threadIdx.x;
    const int warp = tid >> 5;
    const int lane = tid & 31;
    const int qr   = lane & 3;      // threadID_in_group
    const int gp   = lane >> 2;     // groupID

    float* pool = g_pool[br];

    // Stage W2^T: W2 is [k][n] row-major; store W2T[n*72 + k] (fp16).
    for (int idx = tid; idx < 64 * 64; idx += 32 * BWARPS) {
        int k = idx >> 6, n = idx & 63;
        W2T[n * 72 + k] = __float2half_rn(W2[idx]);
    }
    if (tid < 64) b2s[tid] = b2[tid];
    __syncthreads();

    const uint32_t* W2T32 = (const uint32_t*)W2T;
    __half* myTiles = Tiles + warp * (2 * 16 * 72);  // tile t at +t*1152 halves

    const int grow = lane >> 3;     // row-group within coalesced LDG
    const int qb   = lane & 7;      // 16B chunk within 128B row

    const int nChunks = (nE + 31) >> 5;
    const int STRIDE = gridDim.x * BWARPS;

    for (int ch = blockIdx.x * BWARPS + warp; ch < nChunks; ch += STRIDE) {
        const int e0 = ch << 5;

        // Edge indices for both tiles (lanes 0..15: i; lanes 16..31: j).
        int ivt[2];
        #pragma unroll
        for (int t = 0; t < 2; t++) {
            const int eb = e0 + t * 16;
            if (lane < 16) ivt[t] = (eb + lane < nE) ? __ldcs(ei + eb + lane) : -1;
            else           ivt[t] = (eb + lane - 16 < nE) ? __ldcs(ei + nE + eb + lane - 16) : 0;
        }

        // ---- gather BOTH tiles (16 independent LDG.128 -> MLP 16) ----
        #pragma unroll
        for (int t = 0; t < 2; t++) {
            __half* Hsw = myTiles + t * 1152;
            #pragma unroll
            for (int gg = 0; gg < 4; gg++) {
                int e = gg * 4 + grow;
                int i = __shfl_sync(0xFFFFFFFFu, ivt[t], e);
                int j = __shfl_sync(0xFFFFFFFFu, ivt[t], e + 16);
                uint4 u = make_uint4(0u, 0u, 0u, 0u);
                uint4 v = make_uint4(0u, 0u, 0u, 0u);
                if (i >= 0) {
                    u = *(const uint4*)(g_UVh + (size_t)i * 256 + br * 128 + qb * 8);
                    v = *(const uint4*)(g_UVh + (size_t)j * 256 + br * 128 + 64 + qb * 8);
                }
                uint4 h;   // relu(0+0)=0 handles invalid edges
                h.x = hrelu_add(u.x, v.x);
                h.y = hrelu_add(u.y, v.y);
                h.z = hrelu_add(u.z, v.z);
                h.w = hrelu_add(u.w, v.w);
                *(uint4*)(Hsw + e * 72 + qb * 8) = h;
            }
        }
        __syncwarp();

        // ---- per tile: MMA + epilogue ----
        #pragma unroll
        for (int t = 0; t < 2; t++) {
            const uint32_t* Hw32 = (const uint32_t*)(myTiles + t * 1152); // stride 36

            float acc[8][4];
            #pragma unroll
            for (int nt = 0; nt < 8; nt++)
                #pragma unroll
                for (int q = 0; q < 4; q++) acc[nt][q] = 0.f;

            #pragma unroll
            for (int kt = 0; kt < 4; kt++) {
                const int c = kt * 8 + qr;
                uint32_t a[4];
                a[0] = Hw32[gp * 36 + c];
                a[1] = Hw32[(gp + 8) * 36 + c];
                a[2] = Hw32[gp * 36 + c + 4];
                a[3] = Hw32[(gp + 8) * 36 + c + 4];
                #pragma unroll
                for (int nt = 0; nt < 8; nt++) {
                    uint32_t b0 = W2T32[(nt * 8 + gp) * 36 + kt * 8 + qr];
                    uint32_t b1 = W2T32[(nt * 8 + gp) * 36 + kt * 8 + qr + 4];
                    mma_f16(acc[nt], a, b0, b1);
                }
            }

            // epilogue: relu(D + b2), zero-skip + filtered segment-max
            int i1 = __shfl_sync(0xFFFFFFFFu, ivt[t], gp);       // edge gp
            int i2 = __shfl_sync(0xFFFFFFFFu, ivt[t], gp + 8);   // edge gp+8
            if (i1 >= 0) {
                float* pr = pool + (size_t)i1 * 64 + qr * 2;
                #pragma unroll
                for (int nt = 0; nt < 8; nt++) {
                    float2 bb = *(const float2*)(b2s + nt * 8 + qr * 2);
                    float va = fmaxf(acc[nt][0] + bb.x, 0.f);
                    float vb = fmaxf(acc[nt][1] + bb.y, 0.f);
                    if (va > 0.f || vb > 0.f) {   // pool >= 0: zero never wins
                        float2 cur = __ldcg((const float2*)(pr + nt * 8));
                        // pool only grows; stale read >= v proves final max >= v.
                        if (va > cur.x) atomicMax((int*)(pr + nt * 8),     __float_as_int(va));
                        if (vb > cur.y) atomicMax((int*)(pr + nt * 8 + 1), __float_as_int(vb));
                    }
                }
            }
            if (i2 >= 0) {
                float* pr = pool + (size_t)i2 * 64 + qr * 2;
                #pragma unroll
                for (int nt = 0; nt < 8; nt++) {
                    float2 bb = *(const float2*)(b2s + nt * 8 + qr * 2);
                    float va = fmaxf(acc[nt][2] + bb.x, 0.f);
                    float vb = fmaxf(acc[nt][3] + bb.y, 0.f);
                    if (va > 0.f || vb > 0.f) {
                        float2 cur = __ldcg((const float2*)(pr + nt * 8));
                        if (va > cur.x) atomicMax((int*)(pr + nt * 8),     __float_as_int(va));
                        if (vb > cur.y) atomicMax((int*)(pr + nt * 8 + 1), __float_as_int(vb));
                    }
                }
            }
        }
        __syncwarp();   // all tile reads done before next chunk's STS
    }
}

// ---------------------------------------------------------------------------
// Stage 3: out = relu([pool_t | pool_g] @ Wf + bf)   (fp32, 2 CTAs/SM)
// ---------------------------------------------------------------------------
__global__ __launch_bounds__(256, 2)
void final_kernel(const float* __restrict__ Wf, const float* __restrict__ bf,
                  float* __restrict__ out, int nN)
{
    extern __shared__ float sm[];
    float* Wfs = sm;                // 128 x 64
    float* Ns  = Wfs + 128 * 64;    // 128 x 132

    const int tid = threadIdx.x;
    const int tx  = tid & 15;
    const int ty  = tid >> 4;

    for (int idx = tid; idx < 128 * 64; idx += 256) Wfs[idx] = Wf[idx];
    const float4 bfv = *(const float4*)(bf + 4 * tx);

    const int base = blockIdx.x * 128;
    for (int idx = tid; idx < 128 * 16; idx += 256) {
        int nd = idx >> 4, q = idx & 15;
        float4 a = make_float4(0.f, 0.f, 0.f, 0.f);
        float4 b = make_float4(0.f, 0.f, 0.f, 0.f);
        if (base + nd < nN) {
            a = *(const float4*)(g_pool[0] + (size_t)(base + nd) * 64 + 4 * q);
            b = *(const float4*)(g_pool[1] + (size_t)(base + nd) * 64 + 4 * q);
        }
        *(float4*)(Ns + nd * 132 + 4 * q) = a;
        *(float4*)(Ns + nd * 132 + 64 + 4 * q) = b;
    }
    __syncthreads();

    float acc[8][4];
    #pragma unroll
    for (int ii = 0; ii < 8; ii++)
        #pragma unroll
        for (int j = 0; j < 4; j++) acc[ii][j] = 0.f;

    #pragma unroll 4
    for (int k = 0; k < 128; k += 4) {
        float4 w0 = *(const float4*)(Wfs + (k + 0) * 64 + 4 * tx);
        float4 w1 = *(const float4*)(Wfs + (k + 1) * 64 + 4 * tx);
        float4 w2 = *(const float4*)(Wfs + (k + 2) * 64 + 4 * tx);
        float4 w3 = *(const float4*)(Wfs + (k + 3) * 64 + 4 * tx);
        #pragma unroll
        for (int ii = 0; ii < 8; ii++) {
            float4 a = *(const float4*)(Ns + (8 * ty + ii) * 132 + k);
            acc[ii][0] += a.x * w0.x + a.y * w1.x + a.z * w2.x + a.w * w3.x;
            acc[ii][1] += a.x * w0.y + a.y * w1.y + a.z * w2.y + a.w * w3.y;
            acc[ii][2] += a.x * w0.z + a.y * w1.z + a.z * w2.z + a.w * w3.z;
            acc[ii][3] += a.x * w0.w + a.y * w1.w + a.z * w2.w + a.w * w3.w;
        }
    }

    #pragma unroll
    for (int ii = 0; ii < 8; ii++) {
        int node = base + 8 * ty + ii;
        if (node < nN) {
            float4 o;
            o.x = fmaxf(acc[ii][0] + bfv.x, 0.f);
            o.y = fmaxf(acc[ii][1] + bfv.y, 0.f);
            o.z = fmaxf(acc[ii][2] + bfv.z, 0.f);
            o.w = fmaxf(acc[ii][3] + bfv.w, 0.f);
            *(float4*)(out + (size_t)node * 64 + 4 * tx) = o;
        }
    }
}

// ---------------------------------------------------------------------------
extern "C" void kernel_launch(void* const* d_in, const int* in_sizes, int n_in,
                              void* d_out, int out_size)
{
    const float* x   = (const float*)d_in[0];
    const int*   eit = (const int*)d_in[1];
    const int*   eig = (const int*)d_in[2];
    const float* Wt1 = (const float*)d_in[3];
    const float* bt1 = (const float*)d_in[4];
    const float* Wt2 = (const float*)d_in[5];
    const float* bt2 = (const float*)d_in[6];
    const float* Wg1 = (const float*)d_in[7];
    const float* bg1 = (const float*)d_in[8];
    const float* Wg2 = (const float*)d_in[9];
    const float* bg2 = (const float*)d_in[10];
    const float* Wf  = (const float*)d_in[11];
    const float* bf  = (const float*)d_in[12];
    float* out = (float*)d_out;

    const int nN = in_sizes[0] / 64;
    const int nE = in_sizes[1] / 2;

    void* poolPtr = nullptr;
    cudaGetSymbolAddress(&poolPtr, g_pool);
    cudaMemsetAsync(poolPtr, 0, sizeof(float) * 2 * (size_t)N_MAX * 64, 0);

    const int smemN = (64 * 260 + 128 * 68) * 4;
    cudaFuncSetAttribute(node_kernel,
                         cudaFuncAttributeMaxDynamicSharedMemorySize, smemN);
    node_kernel<<<(nN + 127) / 128, 512, smemN>>>(x, Wt1, Wg1, bt1, bg1, nN);

    // Sequential branch phases: each phase's working set is L2-resident.
    cudaFuncSetAttribute(branch_kernel,
                         cudaFuncAttributeMaxDynamicSharedMemorySize, SMEM_BRANCH);
    branch_kernel<<<444, 32 * BWARPS, SMEM_BRANCH>>>(eit, Wt2, bt2, nE, 0);
    branch_kernel<<<444, 32 * BWARPS, SMEM_BRANCH>>>(eig, Wg2, bg2, nE, 1);

    const int smemF = (128 * 64 + 128 * 132) * 4;
    cudaFuncSetAttribute(final_kernel,
                         cudaFuncAttributeMaxDynamicSharedMemorySize, smemF);
    final_kernel<<<(nN + 127) / 128, 256, smemF>>>(Wf, bf, out, nN);
}